// round 6
// baseline (speedup 1.0000x reference)
#include <cuda_runtime.h>
#include <cuda_bf16.h>

// SPU activation bounds (RIAI SPU-Trainable), collapsed to elementwise.
//
// The reference's (bs,n,n+1) matrices are diagonal+bias, so backsubstitution
// reduces to:  al = lw*(lw>0?l:u)+lb ;  au = uw*(uw>0?u:l)+ub.
//
// Identities for x<0 with s = 1/(1+e^x):
//   spu(x)  = s - 1
//   spu'(x) = -0.5/(cosh(x)+1) = s*s - s
// (x <= -50: e^x underflows -> s=1 -> grad=0, matching the reference cutoff.)
//
// The reference's 20-step bisection refines [l,0] on the dyadic 2^-20 grid.
// Quad-section (3 independent probes/step, 10 steps, 4^-10 = 2^-20) lands on
// the SAME grid with half the serial chain and 3-way MUFU ILP per step.
//
// Fully branchless (FSEL only): every warp contains a crossing lane with
// probability ~1, so branches only add BSSY/BSYNC cost. Masked-lane inputs
// mirror the reference's own masking (it runs the binsearch on all lanes).
//
// 2 elements/thread (float2 in, float4 out): two independent bisection
// chains interleave in-register -> 6-way MUFU ILP to hide the EX2/RCP
// latency that limited the previous (latency-bound, issue=40%) kernel.

__device__ __forceinline__ float fsigmoid(float x) {
    return 1.0f / (1.0f + __expf(-x));
}

// spu(x), branchless, any sign.
__device__ __forceinline__ float fspu(float x) {
    float s   = 1.0f / (1.0f + __expf(x));
    float neg = s - 1.0f;
    float pos = x * x - 0.5f;
    return (x >= 0.0f) ? pos : neg;
}

// Tangent line (a,b) at x0, branchless, any sign.
__device__ __forceinline__ void fspu_tangent(float x0, float& a, float& b) {
    float s  = 1.0f / (1.0f + __expf(x0));
    float ga = s * s - s;            // grad, x0 < 0
    float fa = s - 1.0f;             // spu,  x0 < 0
    float gp = 2.0f * x0;            // grad, x0 >= 0
    float fp = x0 * x0 - 0.5f;       // spu,  x0 >= 0
    a = (x0 >= 0.0f) ? gp : ga;
    b = ((x0 >= 0.0f) ? fp : fa) - a * x0;
}

// One element: returns (al, au). Fully straight-line code (selects only).
__device__ __forceinline__ float2 spu_elem(float l, float u,
                                           float tlr, float tur)
{
    float tl = fsigmoid(4.0f * tlr);
    float tu = fsigmoid(4.0f * tur);

    float yl = fspu(l);
    float yu = fspu(u);

    // secant (endpoint) line
    float ea = (yu - yl) / (u - l + 1e-8f);
    float eb = yl - l * ea;

    bool negative = (u <= 0.0f);
    bool positive = (l >= 0.0f);
    bool crossing = !(negative || positive);

    // T1: tangent at interp(l,u,tl) — positive lower AND crossing-normal lower
    float t1a, t1b;
    fspu_tangent(l + (u - l) * tl, t1a, t1b);
    // T2: tangent at interp(l,u,tu) — negative upper
    float t2a, t2b;
    fspu_tangent(l + (u - l) * tu, t2a, t2b);

    // ---- crossing: quad-section on [l, 0] with masked u (uc = crossing?u:0)
    float uc = crossing ? u : 0.0f;
    float req = fspu(uc);                 // = yu on crossing lanes
    float lo = l;
    float w  = -l;
    #pragma unroll
    for (int it = 0; it < 10; ++it) {
        float q  = 0.25f * w;
        float c1 = lo + q;
        float c2 = lo + 2.0f * q;
        float c3 = lo + 3.0f * q;

        float s1 = 1.0f / (1.0f + __expf(c1));
        float s2 = 1.0f / (1.0f + __expf(c2));
        float s3 = 1.0f / (1.0f + __expf(c3));
        float a1 = s1 * s1 - s1;
        float a2 = s2 * s2 - s2;
        float a3 = s3 * s3 - s3;
        // tangent value at uc:  a*(uc - c) + (s - 1)
        float f1 = a1 * (uc - c1) + (s1 - 1.0f);
        float f2 = a2 * (uc - c2) + (s2 - 1.0f);
        float f3 = a3 * (uc - c3) + (s3 - 1.0f);

        float k = ((f1 >= req) ? 1.0f : 0.0f)
                + ((f2 >= req) ? 1.0f : 0.0f)
                + ((f3 >= req) ? 1.0f : 0.0f);
        lo = lo + k * q;
        w  = q;
    }
    float u_end = lo;

    // crossing upper: tangent at interp(l, u_end, tu); secant fallback
    float ua, ub_;
    fspu_tangent(l + (u_end - l) * tu, ua, ub_);
    bool not_cov = (ua * uc + ub_) <= req;
    float cr_uw = not_cov ? ea : ua;
    float cr_ub = not_cov ? eb : ub_;

    // crossing lower: T1 tangent if tl >= threshold, else steep line @ -0.5
    float den = uc - l;
    float threshold = -l / ((den == 0.0f) ? 1.0f : den);
    bool is_normal = (tl >= threshold);

    bool  l_norm = (l <= -1e-5f) || (l > 0.0f);
    float sx     = l_norm ? l : 1.0f;
    float steep  = l_norm ? ((fspu(sx) + 0.5f) / sx) : -0.25f;

    float safe_thr = (threshold == 0.0f) ? 1.0f : threshold;
    float r  = tl / safe_thr;
    float wa = steep * (1.0f - r * r);

    float cr_lw = is_normal ? t1a : wa;
    float cr_lb = is_normal ? t1b : -0.5f;

    // ---- branch combine (exactly one of negative/positive/crossing true)
    float lw = negative ? ea  : (positive ? t1a : cr_lw);
    float lb = negative ? eb  : (positive ? t1b : cr_lb);
    float uw = negative ? t2a : (positive ? ea  : cr_uw);
    float ub = negative ? t2b : (positive ? eb  : cr_ub);

    // diagonal backsubstitution
    float al = lw * ((lw > 0.0f) ? l : u) + lb;
    float au = uw * ((uw > 0.0f) ? u : l) + ub;
    return make_float2(al, au);
}

__global__ void __launch_bounds__(128)
spu_bounds_kernel(const float2* __restrict__ l_in,
                  const float2* __restrict__ u_in,
                  const float2* __restrict__ tl_raw,
                  const float2* __restrict__ tu_raw,
                  float4* __restrict__ out,
                  int n_pairs)
{
    int i = blockIdx.x * blockDim.x + threadIdx.x;
    if (i >= n_pairs) return;

    float2 l2  = l_in[i];
    float2 u2  = u_in[i];
    float2 tl2 = tl_raw[i];
    float2 tu2 = tu_raw[i];

    // two fully independent elements -> 6-way MUFU ILP in the unrolled loops
    float2 r0 = spu_elem(l2.x, u2.x, tl2.x, tu2.x);
    float2 r1 = spu_elem(l2.y, u2.y, tl2.y, tu2.y);

    out[i] = make_float4(r0.x, r0.y, r1.x, r1.y);
}

extern "C" void kernel_launch(void* const* d_in, const int* in_sizes, int n_in,
                              void* d_out, int out_size)
{
    const float2* l  = (const float2*)d_in[0];
    const float2* u  = (const float2*)d_in[1];
    const float2* tl = (const float2*)d_in[2];
    const float2* tu = (const float2*)d_in[3];
    float4* out = (float4*)d_out;

    int n = in_sizes[0];               // 65536 elements (even)
    int n_pairs = n >> 1;              // 32768 threads
    const int threads = 128;
    int blocks = (n_pairs + threads - 1) / threads;

    spu_bounds_kernel<<<blocks, threads>>>(l, u, tl, tu, out, n_pairs);
}

// round 7
// speedup vs baseline: 1.5556x; 1.5556x over previous
#include <cuda_runtime.h>
#include <cuda_bf16.h>

// SPU activation bounds (RIAI SPU-Trainable), collapsed to elementwise.
//
// Backsubstitution of the diagonal+bias matrices reduces to:
//   al = lw*(lw>0?l:u)+lb ;  au = uw*(uw>0?u:l)+ub
//
// Identities for x<0 with s = 1/(1+e^x):
//   spu(x)  = s - 1
//   spu'(x) = -0.5/(cosh(x)+1) = s*s - s
//
// ROUND-7 KEY FIX: every plain '/' previously compiled to the IEEE division
// sequence (~12 insts, ~70-cyc dependent chain) because the harness doesn't
// build with -use_fast_math. All divisions are now __fdividef (MUFU.RCP +
// FMUL). The bisection loop's serial chain drops ~3x.
//
// Quad-section: 10 steps x 3 independent probes refine [l,0] on the same
// 2^-20 dyadic grid as the reference's 20-step bisection (4^10 = 2^20),
// with half the serial chain and 3-way MUFU ILP per step.
//
// 1 element/thread (2048 warps, ~3.5/SMSP): R5 showed ptxas serializes
// multi-element chains at low reg budgets (regs=39); TLP is the reliable
// latency-hiding mechanism here.

__device__ __forceinline__ float frcp1p(float ex) {   // 1/(1+ex), fast
    return __fdividef(1.0f, 1.0f + ex);
}

__device__ __forceinline__ float fsigmoid(float x) {
    return frcp1p(__expf(-x));
}

// spu(x), branchless, any sign.
__device__ __forceinline__ float fspu(float x) {
    float s   = frcp1p(__expf(x));
    float neg = s - 1.0f;
    float pos = x * x - 0.5f;
    return (x >= 0.0f) ? pos : neg;
}

// Tangent line (a,b) at x0, branchless, any sign.
// x0 <= -50: exp underflows -> s=1 -> grad = s*s-s = 0, matching reference.
__device__ __forceinline__ void fspu_tangent(float x0, float& a, float& b) {
    float s  = frcp1p(__expf(x0));
    float ga = s * s - s;            // grad, x0 < 0
    float fa = s - 1.0f;             // spu,  x0 < 0
    float gp = 2.0f * x0;            // grad, x0 >= 0
    float fp = x0 * x0 - 0.5f;       // spu,  x0 >= 0
    a = (x0 >= 0.0f) ? gp : ga;
    b = ((x0 >= 0.0f) ? fp : fa) - a * x0;
}

__global__ void __launch_bounds__(128)
spu_bounds_kernel(const float* __restrict__ l_in,
                  const float* __restrict__ u_in,
                  const float* __restrict__ tl_raw,
                  const float* __restrict__ tu_raw,
                  float2* __restrict__ out,
                  int n_total)
{
    int i = blockIdx.x * blockDim.x + threadIdx.x;
    if (i >= n_total) return;

    float l = l_in[i];
    float u = u_in[i];
    float tl = fsigmoid(4.0f * tl_raw[i]);
    float tu = fsigmoid(4.0f * tu_raw[i]);

    float yl = fspu(l);
    float yu = fspu(u);

    // secant (endpoint) line — fast division
    float ea = __fdividef(yu - yl, u - l + 1e-8f);
    float eb = yl - l * ea;

    bool negative = (u <= 0.0f);
    bool positive = (l >= 0.0f);
    bool crossing = !(negative || positive);

    // T1: tangent at interp(l,u,tl) — positive lower / crossing-normal lower
    float t1a, t1b;
    fspu_tangent(l + (u - l) * tl, t1a, t1b);
    // T2: tangent at interp(l,u,tu) — negative upper
    float t2a, t2b;
    fspu_tangent(l + (u - l) * tu, t2a, t2b);

    // ---- crossing: quad-section on [l, 0] with masked u (uc = crossing?u:0)
    float uc  = crossing ? u : 0.0f;
    float req = fspu(uc);                 // = yu on crossing lanes
    float lo = l;
    float w  = -l;
    #pragma unroll
    for (int it = 0; it < 10; ++it) {
        float q  = 0.25f * w;
        float c1 = lo + q;
        float c2 = lo + 2.0f * q;
        float c3 = lo + 3.0f * q;

        // three independent probes (c < 0 always): EX2 + RCP each
        float s1 = frcp1p(__expf(c1));
        float s2 = frcp1p(__expf(c2));
        float s3 = frcp1p(__expf(c3));
        float a1 = s1 * s1 - s1;
        float a2 = s2 * s2 - s2;
        float a3 = s3 * s3 - s3;
        // tangent value at uc:  a*(uc - c) + (s - 1)
        float f1 = a1 * (uc - c1) + (s1 - 1.0f);
        float f2 = a2 * (uc - c2) + (s2 - 1.0f);
        float f3 = a3 * (uc - c3) + (s3 - 1.0f);

        float k = ((f1 >= req) ? 1.0f : 0.0f)
                + ((f2 >= req) ? 1.0f : 0.0f)
                + ((f3 >= req) ? 1.0f : 0.0f);
        lo = lo + k * q;
        w  = q;
    }
    float u_end = lo;

    // crossing upper: tangent at interp(l, u_end, tu); secant fallback
    float ua, ub_;
    fspu_tangent(l + (u_end - l) * tu, ua, ub_);
    bool not_cov = (ua * uc + ub_) <= req;
    float cr_uw = not_cov ? ea : ua;
    float cr_ub = not_cov ? eb : ub_;

    // crossing lower: T1 tangent if tl >= threshold, else steep line @ -0.5
    float den = uc - l;
    float threshold = __fdividef(-l, (den == 0.0f) ? 1.0f : den);
    bool is_normal = (tl >= threshold);

    // steep = (spu(l)+0.5)/l for "normal" l (l<=-1e-5 or l>0), else -0.25
    bool  l_norm = (l <= -1e-5f) || (l > 0.0f);
    float steep  = l_norm ? __fdividef(yl + 0.5f, l) : -0.25f;

    float safe_thr = (threshold == 0.0f) ? 1.0f : threshold;
    float r  = __fdividef(tl, safe_thr);
    float wa = steep * (1.0f - r * r);

    float cr_lw = is_normal ? t1a : wa;
    float cr_lb = is_normal ? t1b : -0.5f;

    // ---- combine (exactly one of negative/positive/crossing true)
    float lw = negative ? ea  : (positive ? t1a : cr_lw);
    float lb = negative ? eb  : (positive ? t1b : cr_lb);
    float uw = negative ? t2a : (positive ? ea  : cr_uw);
    float ub = negative ? t2b : (positive ? eb  : cr_ub);

    // diagonal backsubstitution
    float al = lw * ((lw > 0.0f) ? l : u) + lb;
    float au = uw * ((uw > 0.0f) ? u : l) + ub;

    out[i] = make_float2(al, au);
}

extern "C" void kernel_launch(void* const* d_in, const int* in_sizes, int n_in,
                              void* d_out, int out_size)
{
    const float* l  = (const float*)d_in[0];
    const float* u  = (const float*)d_in[1];
    const float* tl = (const float*)d_in[2];
    const float* tu = (const float*)d_in[3];
    float2* out = (float2*)d_out;

    int n = in_sizes[0];               // 64 * 1024 = 65536 elements
    const int threads = 128;
    int blocks = (n + threads - 1) / threads;   // 512 CTAs

    spu_bounds_kernel<<<blocks, threads>>>(l, u, tl, tu, out, n);
}

// round 8
// speedup vs baseline: 1.6154x; 1.0385x over previous
#include <cuda_runtime.h>
#include <cuda_bf16.h>

// SPU activation bounds (RIAI SPU-Trainable), collapsed to elementwise.
//
// Backsubstitution of the diagonal+bias matrices reduces to:
//   al = lw*(lw>0?l:u)+lb ;  au = uw*(uw>0?u:l)+ub
//
// Identities for x<0 with s = 1/(1+e^x), E = 1+e^x:
//   spu(x)  = s - 1
//   spu'(x) = -0.5/(cosh(x)+1) = s*s - s = -e^x / E^2
//
// The reference's 20-step bisection refines [l,0] on the 2^-20 dyadic grid.
// This kernel uses 8-ary section: 7 steps x 7 independent probes (8^7=2^21,
// a refinement of the same grid) -> 7-step serial chain, 7-way ILP/step.
//
// DIVISION-FREE PROBE: covering test  a*(uc-c) + s - 1 >= req  multiplied
// by E^2 > 0 becomes the polynomial sign test
//     E*(A*E + (1-d)) + d >= 0,   A = -(1+req), d = uc - c.
// Only one EX2 per probe; no MUFU.RCP in the loop. lo is also tracked in
// log2 domain (lo2, q2) so the probe exponent is a single FFMA before EX2.
//
// All remaining divisions are __fdividef (single MUFU.RCP), per the R6 win.

__device__ __forceinline__ float frcp1p(float ex) {   // 1/(1+ex), fast
    return __fdividef(1.0f, 1.0f + ex);
}

__device__ __forceinline__ float fsigmoid(float x) {
    return frcp1p(__expf(-x));
}

// spu(x), branchless, any sign.
__device__ __forceinline__ float fspu(float x) {
    float s   = frcp1p(__expf(x));
    float neg = s - 1.0f;
    float pos = x * x - 0.5f;
    return (x >= 0.0f) ? pos : neg;
}

// Tangent line (a,b) at x0, branchless, any sign.
// x0 <= -50: exp underflows -> s=1 -> grad = s*s-s = 0, matching reference.
__device__ __forceinline__ void fspu_tangent(float x0, float& a, float& b) {
    float s  = frcp1p(__expf(x0));
    float ga = s * s - s;            // grad, x0 < 0
    float fa = s - 1.0f;             // spu,  x0 < 0
    float gp = 2.0f * x0;            // grad, x0 >= 0
    float fp = x0 * x0 - 0.5f;       // spu,  x0 >= 0
    a = (x0 >= 0.0f) ? gp : ga;
    b = ((x0 >= 0.0f) ? fp : fa) - a * x0;
}

#define LOG2E 1.4426950408889634f

__global__ void __launch_bounds__(64)
spu_bounds_kernel(const float* __restrict__ l_in,
                  const float* __restrict__ u_in,
                  const float* __restrict__ tl_raw,
                  const float* __restrict__ tu_raw,
                  float2* __restrict__ out,
                  int n_total)
{
    int i = blockIdx.x * blockDim.x + threadIdx.x;
    if (i >= n_total) return;

    float l = l_in[i];
    float u = u_in[i];
    float tl = fsigmoid(4.0f * tl_raw[i]);
    float tu = fsigmoid(4.0f * tu_raw[i]);

    float yl = fspu(l);
    float yu = fspu(u);

    // secant (endpoint) line
    float ea = __fdividef(yu - yl, u - l + 1e-8f);
    float eb = yl - l * ea;

    bool negative = (u <= 0.0f);
    bool positive = (l >= 0.0f);
    bool crossing = !(negative || positive);

    // T1: tangent at interp(l,u,tl) — positive lower / crossing-normal lower
    float t1a, t1b;
    fspu_tangent(l + (u - l) * tl, t1a, t1b);
    // T2: tangent at interp(l,u,tu) — negative upper
    float t2a, t2b;
    fspu_tangent(l + (u - l) * tu, t2a, t2b);

    // ---- crossing search: largest c in [l,0] whose tangent covers
    // (uc, spu(uc)), with uc = crossing ? u : 0 (reference's masking).
    float uc  = crossing ? u : 0.0f;
    float req = fspu(uc);                 // = yu on crossing lanes
    float A   = -1.0f - req;              // poly coefficient
    float one_m_uc = 1.0f - uc;

    float lo  = l;
    float w   = -l;
    float lo2 = l  * LOG2E;               // log2-domain mirror of lo
    float w2  = -l * LOG2E;

    #pragma unroll
    for (int it = 0; it < 7; ++it) {
        float q  = 0.125f * w;
        float q2 = 0.125f * w2;
        float G  = one_m_uc + lo;         // 1 - d_m = G + m*q

        float k = 0.0f;
        #pragma unroll
        for (int m = 1; m <= 7; ++m) {
            float fm = (float)m;
            float e  = exp2f(fmaf(fm, q2, lo2));   // e^{lo + m q}
            float E  = e + 1.0f;
            float g  = fmaf(fm, q, G);             // 1 - d
            float d  = 1.0f - g;                   // uc - c
            // sign test:  A*E^2 + E*(1-d) + d  >= 0  <=>  tangent covers
            float v  = fmaf(E, fmaf(A, E, g), d);
            k += (v >= 0.0f) ? 1.0f : 0.0f;
        }
        lo  = fmaf(k, q,  lo);
        lo2 = fmaf(k, q2, lo2);
        w   = q;
        w2  = q2;
    }
    float u_end = lo;

    // crossing upper: tangent at interp(l, u_end, tu); secant fallback
    float ua, ub_;
    fspu_tangent(l + (u_end - l) * tu, ua, ub_);
    bool not_cov = (ua * uc + ub_) <= req;
    float cr_uw = not_cov ? ea : ua;
    float cr_ub = not_cov ? eb : ub_;

    // crossing lower: T1 tangent if tl >= threshold, else steep line @ -0.5
    float den = uc - l;
    float threshold = __fdividef(-l, (den == 0.0f) ? 1.0f : den);
    bool is_normal = (tl >= threshold);

    // steep = (spu(l)+0.5)/l for "normal" l (l<=-1e-5 or l>0), else -0.25
    bool  l_norm = (l <= -1e-5f) || (l > 0.0f);
    float steep  = l_norm ? __fdividef(yl + 0.5f, l) : -0.25f;

    float safe_thr = (threshold == 0.0f) ? 1.0f : threshold;
    float r  = __fdividef(tl, safe_thr);
    float wa = steep * (1.0f - r * r);

    float cr_lw = is_normal ? t1a : wa;
    float cr_lb = is_normal ? t1b : -0.5f;

    // ---- combine (exactly one of negative/positive/crossing true)
    float lw = negative ? ea  : (positive ? t1a : cr_lw);
    float lb = negative ? eb  : (positive ? t1b : cr_lb);
    float uw = negative ? t2a : (positive ? ea  : cr_uw);
    float ub = negative ? t2b : (positive ? eb  : cr_ub);

    // diagonal backsubstitution
    float al = lw * ((lw > 0.0f) ? l : u) + lb;
    float au = uw * ((uw > 0.0f) ? u : l) + ub;

    out[i] = make_float2(al, au);
}

extern "C" void kernel_launch(void* const* d_in, const int* in_sizes, int n_in,
                              void* d_out, int out_size)
{
    const float* l  = (const float*)d_in[0];
    const float* u  = (const float*)d_in[1];
    const float* tl = (const float*)d_in[2];
    const float* tu = (const float*)d_in[3];
    float2* out = (float2*)d_out;

    int n = in_sizes[0];               // 64 * 1024 = 65536 elements
    const int threads = 64;            // 2-warp CTAs: binding SM holds 14
    int blocks = (n + threads - 1) / threads;   // warps, not 16
    spu_bounds_kernel<<<blocks, threads>>>(l, u, tl, tu, out, n);
}

// round 9
// speedup vs baseline: 1.6232x; 1.0048x over previous
#include <cuda_runtime.h>
#include <cuda_bf16.h>

// SPU activation bounds (RIAI SPU-Trainable), collapsed to elementwise.
//
// Backsubstitution of the diagonal+bias matrices reduces to:
//   al = lw*(lw>0?l:u)+lb ;  au = uw*(uw>0?u:l)+ub
//
// Identities for x<0 with s = 1/(1+e^x), E = 1+e^x:
//   spu(x)  = s - 1
//   spu'(x) = -0.5/(cosh(x)+1) = s*s - s = -e^x / E^2
//
// 8-ary section: 7 steps x 7 independent probes (8^7 = 2^21, a refinement
// of the reference's 20-step-bisection 2^-20 grid; validated at rel_err
// 9.9e-8 in an earlier round).
//
// DIVISION-FREE PROBE: covering test a*(uc-c) + s - 1 >= req, multiplied by
// E^2 > 0, becomes the polynomial sign test
//     E*(A*E + g) + (1 - g) >= 0,   A = -(1+req), g = 1 - (uc - c).
// ROUND-9 FIX: the probe exponential is a raw MUFU via inline PTX
// ex2.approx.ftz.f32 — the previous round accidentally used libm exp2f()
// (~20-instruction software polynomial), tripling the in-loop instruction
// count. With log2-domain tracking of lo (lo2, q2), each probe is exactly
// 1 FFMA + 1 MUFU.EX2 + ~6 FMA-class ops.
//
// All remaining divisions are __fdividef (single MUFU.RCP).

__device__ __forceinline__ float fex2(float x) {      // 2^x, one MUFU op
    float y;
    asm("ex2.approx.ftz.f32 %0, %1;" : "=f"(y) : "f"(x));
    return y;
}

__device__ __forceinline__ float frcp1p(float ex) {   // 1/(1+ex), fast
    return __fdividef(1.0f, 1.0f + ex);
}

__device__ __forceinline__ float fsigmoid(float x) {
    return frcp1p(__expf(-x));
}

// spu(x), branchless, any sign.
__device__ __forceinline__ float fspu(float x) {
    float s   = frcp1p(__expf(x));
    float neg = s - 1.0f;
    float pos = x * x - 0.5f;
    return (x >= 0.0f) ? pos : neg;
}

// Tangent line (a,b) at x0, branchless, any sign.
// x0 <= -50: exp underflows -> s=1 -> grad = s*s-s = 0, matching reference.
__device__ __forceinline__ void fspu_tangent(float x0, float& a, float& b) {
    float s  = frcp1p(__expf(x0));
    float ga = s * s - s;            // grad, x0 < 0
    float fa = s - 1.0f;             // spu,  x0 < 0
    float gp = 2.0f * x0;            // grad, x0 >= 0
    float fp = x0 * x0 - 0.5f;       // spu,  x0 >= 0
    a = (x0 >= 0.0f) ? gp : ga;
    b = ((x0 >= 0.0f) ? fp : fa) - a * x0;
}

#define LOG2E 1.4426950408889634f

__global__ void __launch_bounds__(128)
spu_bounds_kernel(const float* __restrict__ l_in,
                  const float* __restrict__ u_in,
                  const float* __restrict__ tl_raw,
                  const float* __restrict__ tu_raw,
                  float2* __restrict__ out,
                  int n_total)
{
    int i = blockIdx.x * blockDim.x + threadIdx.x;
    if (i >= n_total) return;

    float l = l_in[i];
    float u = u_in[i];
    float tl = fsigmoid(4.0f * tl_raw[i]);
    float tu = fsigmoid(4.0f * tu_raw[i]);

    float yl = fspu(l);
    float yu = fspu(u);

    // secant (endpoint) line
    float ea = __fdividef(yu - yl, u - l + 1e-8f);
    float eb = yl - l * ea;

    bool negative = (u <= 0.0f);
    bool positive = (l >= 0.0f);
    bool crossing = !(negative || positive);

    // T1: tangent at interp(l,u,tl) — positive lower / crossing-normal lower
    float t1a, t1b;
    fspu_tangent(l + (u - l) * tl, t1a, t1b);
    // T2: tangent at interp(l,u,tu) — negative upper
    float t2a, t2b;
    fspu_tangent(l + (u - l) * tu, t2a, t2b);

    // ---- crossing search: largest c in [l,0] whose tangent covers
    // (uc, spu(uc)), with uc = crossing ? u : 0 (reference's masking).
    float uc  = crossing ? u : 0.0f;
    float req = fspu(uc);                 // = yu on crossing lanes
    float A   = -1.0f - req;              // poly coefficient
    float one_m_uc = 1.0f - uc;

    float lo  = l;
    float w   = -l;
    float lo2 = l  * LOG2E;               // log2-domain mirror of lo
    float w2  = -l * LOG2E;

    #pragma unroll
    for (int it = 0; it < 7; ++it) {
        float q  = 0.125f * w;
        float q2 = 0.125f * w2;
        float G  = one_m_uc + lo;         // g_m = G + m*q

        float k = 0.0f;
        #pragma unroll
        for (int m = 1; m <= 7; ++m) {
            float fm = (float)m;
            float e  = fex2(fmaf(fm, q2, lo2));    // e^{lo + m q}  (1 MUFU)
            float E  = e + 1.0f;
            float g  = fmaf(fm, q, G);             // 1 - (uc - c)
            // sign test:  E*(A*E + g) + (1 - g) >= 0  <=>  tangent covers
            float v  = fmaf(E, fmaf(A, E, g), 1.0f - g);
            k += (v >= 0.0f) ? 1.0f : 0.0f;
        }
        lo  = fmaf(k, q,  lo);
        lo2 = fmaf(k, q2, lo2);
        w   = q;
        w2  = q2;
    }
    float u_end = lo;

    // crossing upper: tangent at interp(l, u_end, tu); secant fallback
    float ua, ub_;
    fspu_tangent(l + (u_end - l) * tu, ua, ub_);
    bool not_cov = (ua * uc + ub_) <= req;
    float cr_uw = not_cov ? ea : ua;
    float cr_ub = not_cov ? eb : ub_;

    // crossing lower: T1 tangent if tl >= threshold, else steep line @ -0.5
    float den = uc - l;
    float threshold = __fdividef(-l, (den == 0.0f) ? 1.0f : den);
    bool is_normal = (tl >= threshold);

    // steep = (spu(l)+0.5)/l for "normal" l (l<=-1e-5 or l>0), else -0.25
    bool  l_norm = (l <= -1e-5f) || (l > 0.0f);
    float steep  = l_norm ? __fdividef(yl + 0.5f, l) : -0.25f;

    float safe_thr = (threshold == 0.0f) ? 1.0f : threshold;
    float r  = __fdividef(tl, safe_thr);
    float wa = steep * (1.0f - r * r);

    float cr_lw = is_normal ? t1a : wa;
    float cr_lb = is_normal ? t1b : -0.5f;

    // ---- combine (exactly one of negative/positive/crossing true)
    float lw = negative ? ea  : (positive ? t1a : cr_lw);
    float lb = negative ? eb  : (positive ? t1b : cr_lb);
    float uw = negative ? t2a : (positive ? ea  : cr_uw);
    float ub = negative ? t2b : (positive ? eb  : cr_ub);

    // diagonal backsubstitution
    float al = lw * ((lw > 0.0f) ? l : u) + lb;
    float au = uw * ((uw > 0.0f) ? u : l) + ub;

    out[i] = make_float2(al, au);
}

extern "C" void kernel_launch(void* const* d_in, const int* in_sizes, int n_in,
                              void* d_out, int out_size)
{
    const float* l  = (const float*)d_in[0];
    const float* u  = (const float*)d_in[1];
    const float* tl = (const float*)d_in[2];
    const float* tu = (const float*)d_in[3];
    float2* out = (float2*)d_out;

    int n = in_sizes[0];               // 64 * 1024 = 65536 elements
    const int threads = 128;           // best measured config (R6 ncu 5.47us)
    int blocks = (n + threads - 1) / threads;   // 512 CTAs, single wave
    spu_bounds_kernel<<<blocks, threads>>>(l, u, tl, tu, out, n);
}